// round 2
// baseline (speedup 1.0000x reference)
#include <cuda_runtime.h>
#include <cuda_bf16.h>
#include <math.h>

#define S_TOK   1024
#define DIM     2560
#define HD      128
#define NH      20
#define NKV     5
#define QKV_OUT 3840
#define KW      640      // K in int32 words (2560/4)
#define NGRP    20       // scale groups (2560/128)
#define GW      32       // int32 words per group

// ---------------- device scratch (static, no allocation) ----------------
__device__ int   g_wq[QKV_OUT * KW];
__device__ int   g_wo[DIM * KW];
__device__ int   g_qx[S_TOK * KW];
__device__ float g_sx[S_TOK];
__device__ float g_qkv[S_TOK * QKV_OUT];
__device__ float g_qf[S_TOK * NH * HD];
__device__ float g_kf[S_TOK * NKV * HD];
__device__ float g_vf[S_TOK * NKV * HD];
__device__ float g_attn[S_TOK * NH * HD];
__device__ int   g_qa[S_TOK * KW];
__device__ float g_sa[S_TOK];

// ---------------- ternary weight f32 -> packed int8 ----------------
__global__ void conv_w_kernel(const float* __restrict__ w, int rows, int which) {
    int* dst = which ? g_wo : g_wq;
    int total = rows * KW;
    for (int i = blockIdx.x * blockDim.x + threadIdx.x; i < total;
         i += gridDim.x * blockDim.x) {
        int r = i / KW, kw = i - r * KW;
        const float* p = w + (size_t)r * DIM + kw * 4;
        int b0 = (int)p[0], b1 = (int)p[1], b2 = (int)p[2], b3 = (int)p[3];
        dst[i] = (b0 & 0xFF) | ((b1 & 0xFF) << 8) | ((b2 & 0xFF) << 16) | ((b3 & 0xFF) << 24);
    }
}

// ---------------- per-token activation quant ----------------
// which==0: read x (arg), write g_qx/g_sx. which==1: read g_attn, write g_qa/g_sa.
__global__ void quant_kernel(const float* __restrict__ xsrc, int which) {
    int t = blockIdx.x;
    const float* row = which ? (const float*)&g_attn[t * DIM] : (xsrc + (size_t)t * DIM);
    __shared__ float red[8];
    float m = 0.f;
    for (int i = threadIdx.x; i < DIM; i += 256) m = fmaxf(m, fabsf(row[i]));
    #pragma unroll
    for (int o = 16; o; o >>= 1) m = fmaxf(m, __shfl_xor_sync(0xffffffffu, m, o));
    if ((threadIdx.x & 31) == 0) red[threadIdx.x >> 5] = m;
    __syncthreads();
    if (threadIdx.x < 8) {
        m = red[threadIdx.x];
        #pragma unroll
        for (int o = 4; o; o >>= 1) m = fmaxf(m, __shfl_xor_sync(0xffu, m, o));
        if (threadIdx.x == 0) red[0] = m;
    }
    __syncthreads();
    m = fmaxf(red[0], 1e-5f);
    float s = 127.f / m;
    if (threadIdx.x == 0) { if (which) g_sa[t] = s; else g_sx[t] = s; }
    int* q = (which ? g_qa : g_qx) + t * KW;
    for (int w = threadIdx.x; w < KW; w += 256) {
        int pk = 0;
        #pragma unroll
        for (int b = 0; b < 4; b++) {
            float v = row[w * 4 + b] * s;
            int qi = (int)rintf(v);
            qi = min(127, max(-128, qi));
            pk |= (qi & 0xFF) << (8 * b);
        }
        q[w] = pk;
    }
}

// ---------------- int8 x int8 group-scaled GEMM ----------------
// which==0: A=g_qx (1024 x 640w), B=g_wq, ws=ws_qkv, C=g_qkv, N=3840
// which==1: A=g_qa,               B=g_wo, ws=ws_o,   C=dOut,  N=2560
__global__ void gemm_i8_kernel(int which, const float* __restrict__ ws,
                               float* __restrict__ dOut, int N) {
    const int* __restrict__ A = which ? g_qa : g_qx;
    const int* __restrict__ B = which ? g_wo : g_wq;
    const float* __restrict__ sv = which ? g_sa : g_sx;
    float* __restrict__ C = which ? dOut : g_qkv;

    __shared__ __align__(16) int As[GW][68];
    __shared__ __align__(16) int Bs[GW][68];

    int tx = threadIdx.x & 15, ty = threadIdx.x >> 4;
    int rowBase = blockIdx.y * 64, colBase = blockIdx.x * 64;

    float facc[4][4] = {};
    for (int g = 0; g < NGRP; g++) {
        #pragma unroll
        for (int i = 0; i < 8; i++) {
            int p = threadIdx.x + 256 * i;
            int r = p >> 5, kk = p & 31;
            As[kk][r] = A[(rowBase + r) * KW + g * GW + kk];
            Bs[kk][r] = B[(colBase + r) * KW + g * GW + kk];
        }
        __syncthreads();
        int iacc[4][4] = {};
        #pragma unroll 8
        for (int kk = 0; kk < GW; kk++) {
            int4 a = *(const int4*)&As[kk][ty * 4];
            int4 b = *(const int4*)&Bs[kk][tx * 4];
            int av[4] = {a.x, a.y, a.z, a.w};
            int bv[4] = {b.x, b.y, b.z, b.w};
            #pragma unroll
            for (int i = 0; i < 4; i++)
                #pragma unroll
                for (int j = 0; j < 4; j++)
                    iacc[i][j] = __dp4a(av[i], bv[j], iacc[i][j]);
        }
        #pragma unroll
        for (int j = 0; j < 4; j++) {
            float wsc = ws[(colBase + tx * 4 + j) * NGRP + g];
            #pragma unroll
            for (int i = 0; i < 4; i++) facc[i][j] += (float)iacc[i][j] * wsc;
        }
        __syncthreads();
    }
    #pragma unroll
    for (int i = 0; i < 4; i++) {
        float sval = sv[rowBase + ty * 4 + i];
        #pragma unroll
        for (int j = 0; j < 4; j++)
            C[(size_t)(rowBase + ty * 4 + i) * N + colBase + tx * 4 + j] = facc[i][j] / sval;
    }
}

// ---------------- RMSNorm + RoPE (+ V copy) ----------------
__global__ void post_kernel(const float* __restrict__ qnw, const float* __restrict__ knw) {
    int t = blockIdx.x, u = blockIdx.y, d = threadIdx.x;   // 128 threads
    const float* src;
    float* dst;
    const float* nw;
    if (u < NH) {
        src = &g_qkv[t * QKV_OUT + u * HD];
        dst = &g_qf[(t * NH + u) * HD];
        nw = qnw;
    } else if (u < NH + NKV) {
        int kv = u - NH;
        src = &g_qkv[t * QKV_OUT + NH * HD + kv * HD];
        dst = &g_kf[(t * NKV + kv) * HD];
        nw = knw;
    } else {
        int kv = u - NH - NKV;
        g_vf[(t * NKV + kv) * HD + d] = g_qkv[t * QKV_OUT + (NH + NKV) * HD + kv * HD + d];
        return;
    }
    __shared__ float buf[HD];
    __shared__ float red[4];
    float v = src[d];
    float sq = v * v;
    #pragma unroll
    for (int o = 16; o; o >>= 1) sq += __shfl_xor_sync(0xffffffffu, sq, o);
    if ((d & 31) == 0) red[d >> 5] = sq;
    __syncthreads();
    float mean = (red[0] + red[1] + red[2] + red[3]) * (1.f / 128.f);
    float r = rsqrtf(mean + 1e-5f);
    buf[d] = v * r * nw[d];
    __syncthreads();
    int p = d >> 1;
    double inv_freq = exp(-(double)p / 64.0 * log(500000.0));
    double ang = (double)t * inv_freq;
    float c = (float)cos(ang), sn = (float)sin(ang);
    float x0 = buf[p * 2], x1 = buf[p * 2 + 1];
    dst[d] = (d & 1) ? (x0 * sn + x1 * c) : (x0 * c - x1 * sn);
}

// ---------------- causal GQA flash attention (fp32) ----------------
// grid (16 q-tiles, 20 heads), 256 threads, dynamic smem.
#define SWZ(r, ch) ((r) * 32 + ((ch) ^ ((r) & 31)))
#define SMEM_ATTN (3 * 2048 * 16 + (64 * 65 + 3 * 64) * 4)

__global__ void attn_kernel() {
    extern __shared__ float4 smv[];
    float4* Qc = smv;            // 64 rows x 32 chunks (swizzled)
    float4* Kc = Qc + 2048;
    float4* Vc = Kc + 2048;
    float* Ps = (float*)(Vc + 2048);   // 64 x 65
    float* lbuf = Ps + 64 * 65;
    float* mbuf = lbuf + 64;
    float* cbuf = mbuf + 64;

    const int qt = blockIdx.x, hh = blockIdx.y;
    const int g = hh >> 2;
    const int tid = threadIdx.x;
    const int tx = tid & 15, ty = tid >> 4;
    const float scale = 0.08838834764831845f;   // 128^-0.5

    // load Q tile (swizzled float4)
    for (int i = tid; i < 2048; i += 256) {
        int r = i >> 5, ch = i & 31;
        Qc[SWZ(r, ch)] = *(const float4*)&g_qf[((size_t)(qt * 64 + r) * NH + hh) * HD + ch * 4];
    }
    if (tid < 64) { mbuf[tid] = -1e30f; lbuf[tid] = 0.f; }

    float o[4][8];
    #pragma unroll
    for (int i = 0; i < 4; i++)
        #pragma unroll
        for (int k = 0; k < 8; k++) o[i][k] = 0.f;

    __syncthreads();

    for (int kt = 0; kt <= qt; kt++) {
        // load K/V tiles
        for (int i = tid; i < 2048; i += 256) {
            int r = i >> 5, ch = i & 31;
            Kc[SWZ(r, ch)] = *(const float4*)&g_kf[((size_t)(kt * 64 + r) * NKV + g) * HD + ch * 4];
            Vc[SWZ(r, ch)] = *(const float4*)&g_vf[((size_t)(kt * 64 + r) * NKV + g) * HD + ch * 4];
        }
        __syncthreads();

        // scores: thread -> rows ty*4+i, cols tx*4+j
        float sacc[4][4] = {};
        #pragma unroll 4
        for (int ch = 0; ch < 32; ch++) {
            float4 q4[4], k4[4];
            #pragma unroll
            for (int i = 0; i < 4; i++) q4[i] = Qc[SWZ(ty * 4 + i, ch)];
            #pragma unroll
            for (int j = 0; j < 4; j++) k4[j] = Kc[SWZ(tx * 4 + j, ch)];
            #pragma unroll
            for (int i = 0; i < 4; i++)
                #pragma unroll
                for (int j = 0; j < 4; j++)
                    sacc[i][j] += q4[i].x * k4[j].x + q4[i].y * k4[j].y +
                                  q4[i].z * k4[j].z + q4[i].w * k4[j].w;
        }
        #pragma unroll
        for (int i = 0; i < 4; i++) {
            int qg = qt * 64 + ty * 4 + i;
            #pragma unroll
            for (int j = 0; j < 4; j++) {
                int kg = kt * 64 + tx * 4 + j;
                Ps[(ty * 4 + i) * 65 + tx * 4 + j] = (kg <= qg) ? sacc[i][j] * scale : -1e30f;
            }
        }
        __syncthreads();

        // row stats + exp in place: 4 threads per row
        {
            int row = tid >> 2, sub = tid & 3;
            int base = row * 65 + sub * 16;
            float mt = -1e30f;
            #pragma unroll
            for (int c = 0; c < 16; c++) mt = fmaxf(mt, Ps[base + c]);
            mt = fmaxf(mt, __shfl_xor_sync(0xffffffffu, mt, 1));
            mt = fmaxf(mt, __shfl_xor_sync(0xffffffffu, mt, 2));
            float mo = mbuf[row];
            float nm = fmaxf(mo, mt);
            float lt = 0.f;
            #pragma unroll
            for (int c = 0; c < 16; c++) {
                float p = expf(Ps[base + c] - nm);
                Ps[base + c] = p;
                lt += p;
            }
            lt += __shfl_xor_sync(0xffffffffu, lt, 1);
            lt += __shfl_xor_sync(0xffffffffu, lt, 2);
            if (sub == 0) {
                float corr = expf(mo - nm);
                cbuf[row] = corr;
                mbuf[row] = nm;
                lbuf[row] = lbuf[row] * corr + lt;
            }
        }
        __syncthreads();

        // rescale + P @ V : thread -> rows ty*4+i, dims tx*8..tx*8+7
        #pragma unroll
        for (int i = 0; i < 4; i++) {
            float corr = cbuf[ty * 4 + i];
            #pragma unroll
            for (int k = 0; k < 8; k++) o[i][k] *= corr;
        }
        for (int j = 0; j < 64; j++) {
            float4 va = Vc[j * 32 + ((2 * tx) ^ (j & 31))];
            float4 vb = Vc[j * 32 + ((2 * tx + 1) ^ (j & 31))];
            #pragma unroll
            for (int i = 0; i < 4; i++) {
                float p = Ps[(ty * 4 + i) * 65 + j];
                o[i][0] += p * va.x; o[i][1] += p * va.y;
                o[i][2] += p * va.z; o[i][3] += p * va.w;
                o[i][4] += p * vb.x; o[i][5] += p * vb.y;
                o[i][6] += p * vb.z; o[i][7] += p * vb.w;
            }
        }
        __syncthreads();
    }

    #pragma unroll
    for (int i = 0; i < 4; i++) {
        float inv = 1.f / lbuf[ty * 4 + i];
        float4 a, b;
        a.x = o[i][0] * inv; a.y = o[i][1] * inv; a.z = o[i][2] * inv; a.w = o[i][3] * inv;
        b.x = o[i][4] * inv; b.y = o[i][5] * inv; b.z = o[i][6] * inv; b.w = o[i][7] * inv;
        float* dst = &g_attn[(size_t)(qt * 64 + ty * 4 + i) * DIM + hh * HD + tx * 8];
        *(float4*)dst = a;
        *(float4*)(dst + 4) = b;
    }
}

// ---------------- launch ----------------
extern "C" void kernel_launch(void* const* d_in, const int* in_sizes, int n_in,
                              void* d_out, int out_size) {
    const float* x      = (const float*)d_in[0];
    const float* w_qkv  = (const float*)d_in[1];
    const float* ws_qkv = (const float*)d_in[2];
    const float* w_o    = (const float*)d_in[3];
    const float* ws_o   = (const float*)d_in[4];
    const float* qnw    = (const float*)d_in[5];
    const float* knw    = (const float*)d_in[6];
    float* out = (float*)d_out;

    cudaFuncSetAttribute(attn_kernel, cudaFuncAttributeMaxDynamicSharedMemorySize, SMEM_ATTN);

    conv_w_kernel<<<2048, 256>>>(w_qkv, QKV_OUT, 0);
    conv_w_kernel<<<2048, 256>>>(w_o, DIM, 1);
    quant_kernel<<<S_TOK, 256>>>(x, 0);
    gemm_i8_kernel<<<dim3(QKV_OUT / 64, S_TOK / 64), 256>>>(0, ws_qkv, nullptr, QKV_OUT);
    post_kernel<<<dim3(S_TOK, NH + 2 * NKV), 128>>>(qnw, knw);
    attn_kernel<<<dim3(S_TOK / 64, NH), 256, SMEM_ATTN>>>();
    quant_kernel<<<S_TOK, 256>>>(nullptr, 1);
    gemm_i8_kernel<<<dim3(DIM / 64, S_TOK / 64), 256>>>(1, ws_o, out, DIM);
}

// round 3
// speedup vs baseline: 1.6126x; 1.6126x over previous
#include <cuda_runtime.h>
#include <cuda_bf16.h>
#include <math.h>

#define S_TOK   1024
#define DIM     2560
#define HD      128
#define NH      20
#define NKV     5
#define QKV_OUT 3840
#define KW      640      // K in int32 words (2560/4)
#define NGRP    20       // scale groups (2560/128)

// ---------------- device scratch (static, no allocation) ----------------
__device__ int    g_wq[QKV_OUT * KW];
__device__ int    g_wo[DIM * KW];
__device__ int    g_qx[S_TOK * KW];
__device__ float  g_sx[S_TOK];
__device__ float  g_qkv[S_TOK * QKV_OUT];
__device__ float  g_qf[S_TOK * NH * HD];
__device__ float  g_kf[S_TOK * NKV * HD];
__device__ float  g_vf[S_TOK * NKV * HD];
__device__ float  g_attn[S_TOK * NH * HD];
__device__ int    g_qa[S_TOK * KW];
__device__ float  g_sa[S_TOK];
__device__ float2 g_rope[S_TOK * 64];

// ---------------- f32x2 helpers ----------------
__device__ __forceinline__ void fma2(unsigned long long& d, unsigned long long a,
                                     unsigned long long b) {
    asm("fma.rn.f32x2 %0, %1, %2, %3;" : "=l"(d) : "l"(a), "l"(b), "l"(d));
}
__device__ __forceinline__ unsigned long long mul2(unsigned long long a,
                                                   unsigned long long b) {
    unsigned long long d;
    asm("mul.rn.f32x2 %0, %1, %2;" : "=l"(d) : "l"(a), "l"(b));
    return d;
}
__device__ __forceinline__ unsigned long long pk2(float lo, float hi) {
    unsigned long long r;
    asm("mov.b64 %0, {%1, %2};" : "=l"(r) : "r"(__float_as_uint(lo)), "r"(__float_as_uint(hi)));
    return r;
}
__device__ __forceinline__ float2 upk2(unsigned long long v) {
    unsigned lo, hi;
    asm("mov.b64 {%0, %1}, %2;" : "=r"(lo), "=r"(hi) : "l"(v));
    return make_float2(__uint_as_float(lo), __uint_as_float(hi));
}

// ---------------- cp.async helpers ----------------
#define CP16(dst, src)                                                          \
    do {                                                                        \
        unsigned _sa = (unsigned)__cvta_generic_to_shared(dst);                 \
        asm volatile("cp.async.cg.shared.global [%0], [%1], 16;" ::"r"(_sa),    \
                     "l"(src));                                                 \
    } while (0)
#define CPCOMMIT() asm volatile("cp.async.commit_group;")
#define CPWAIT1()  asm volatile("cp.async.wait_group 1;")

// ---------------- ternary weight f32 -> packed int8 (vectorized) ----------------
__global__ void conv_w_kernel(const float* __restrict__ w, int rows, int which) {
    int* dst = which ? g_wo : g_wq;
    int total = rows * KW;
    for (int i = blockIdx.x * blockDim.x + threadIdx.x; i < total;
         i += gridDim.x * blockDim.x) {
        float4 v = *(const float4*)&w[(size_t)i * 4];
        int b0 = (int)v.x, b1 = (int)v.y, b2 = (int)v.z, b3 = (int)v.w;
        dst[i] = (b0 & 0xFF) | ((b1 & 0xFF) << 8) | ((b2 & 0xFF) << 16) | ((b3 & 0xFF) << 24);
    }
}

// ---------------- RoPE table (double precision, tiny) ----------------
__global__ void rope_kernel() {
    int idx = blockIdx.x * 256 + threadIdx.x;   // 65536 total
    int t = idx >> 6, p = idx & 63;
    double inv = exp(-(double)p / 64.0 * log(500000.0));
    double ang = (double)t * inv;
    g_rope[idx] = make_float2((float)cos(ang), (float)sin(ang));
}

// ---------------- per-token activation quant (vectorized) ----------------
__global__ void quant_kernel(const float* __restrict__ xsrc, int which) {
    int t = blockIdx.x;
    const float4* row = which ? (const float4*)&g_attn[t * DIM]
                              : (const float4*)(xsrc + (size_t)t * DIM);
    __shared__ float red[8];
    float m = 0.f;
    for (int i = threadIdx.x; i < KW; i += 256) {
        float4 v = row[i];
        m = fmaxf(m, fmaxf(fmaxf(fabsf(v.x), fabsf(v.y)), fmaxf(fabsf(v.z), fabsf(v.w))));
    }
    #pragma unroll
    for (int o = 16; o; o >>= 1) m = fmaxf(m, __shfl_xor_sync(0xffffffffu, m, o));
    if ((threadIdx.x & 31) == 0) red[threadIdx.x >> 5] = m;
    __syncthreads();
    if (threadIdx.x < 8) {
        m = red[threadIdx.x];
        #pragma unroll
        for (int o = 4; o; o >>= 1) m = fmaxf(m, __shfl_xor_sync(0xffu, m, o));
        if (threadIdx.x == 0) red[0] = m;
    }
    __syncthreads();
    m = fmaxf(red[0], 1e-5f);
    float s = 127.f / m;
    if (threadIdx.x == 0) { if (which) g_sa[t] = s; else g_sx[t] = s; }
    int* q = (which ? g_qa : g_qx) + t * KW;
    for (int w = threadIdx.x; w < KW; w += 256) {
        float4 v = row[w];
        int q0 = min(127, max(-128, (int)rintf(v.x * s)));
        int q1 = min(127, max(-128, (int)rintf(v.y * s)));
        int q2 = min(127, max(-128, (int)rintf(v.z * s)));
        int q3 = min(127, max(-128, (int)rintf(v.w * s)));
        q[w] = (q0 & 0xFF) | ((q1 & 0xFF) << 8) | ((q2 & 0xFF) << 16) | ((q3 & 0xFF) << 24);
    }
}

// ---------------- pipelined int8 group-scaled GEMM ----------------
// Tile: M=128 x N=64, 256 threads, per-thread 8x4 (rows ty*8+i, cols tx+16*j).
// A smem: [2][128][32] words (broadcast reads). B smem: [2][64][32] XOR-swizzled.
#define GEMM_SMEM ((2 * 128 * 32 + 2 * 64 * 32) * 4 + 64 * NGRP * 4 + 128 * 4)

__global__ __launch_bounds__(256, 2) void gemm_i8_kernel(int which,
                                                         const float* __restrict__ ws,
                                                         float* __restrict__ dOut, int N) {
    const int* __restrict__ A = which ? g_qa : g_qx;
    const int* __restrict__ B = which ? g_wo : g_wq;
    const float* __restrict__ sv = which ? g_sa : g_sx;
    float* __restrict__ C = which ? dOut : g_qkv;

    extern __shared__ int smg[];
    int* As = smg;                       // 2*128*32
    int* Bs = As + 2 * 128 * 32;         // 2*64*32
    float* ws_s = (float*)(Bs + 2 * 64 * 32);  // 64*20
    float* sv_s = ws_s + 64 * NGRP;            // 128

    const int tid = threadIdx.x, tx = tid & 15, ty = tid >> 4;
    const int rowBase = blockIdx.y * 128, colBase = blockIdx.x * 64;

    for (int i = tid; i < 64 * NGRP; i += 256) ws_s[i] = ws[colBase * NGRP + i];
    if (tid < 128) sv_s[tid] = sv[rowBase + tid];

    const int* Abase = A + (size_t)rowBase * KW;
    const int* Bbase = B + (size_t)colBase * KW;

    auto issue = [&](int g, int buf) {
        const int* Asrc = Abase + g * 32;
        #pragma unroll
        for (int u = 0; u < 4; u++) {
            int c = tid + 256 * u;
            int r = c >> 3, cw = c & 7;
            CP16(&As[(buf * 128 + r) * 32 + cw * 4], Asrc + r * KW + cw * 4);
        }
        const int* Bsrc = Bbase + g * 32;
        #pragma unroll
        for (int u = 0; u < 2; u++) {
            int c = tid + 256 * u;
            int r = c >> 3, cw = c & 7;
            CP16(&Bs[(buf * 64 + r) * 32 + ((cw ^ (r & 7)) * 4)], Bsrc + r * KW + cw * 4);
        }
    };

    float facc[8][4] = {};
    issue(0, 0);
    CPCOMMIT();

    const int swz = tx & 7;
    for (int g = 0; g < NGRP; g++) {
        int buf = g & 1;
        if (g + 1 < NGRP) issue(g + 1, buf ^ 1);
        CPCOMMIT();
        CPWAIT1();
        __syncthreads();

        int iacc[8][4] = {};
        #pragma unroll
        for (int k4 = 0; k4 < 8; k4++) {
            int4 bv[4];
            #pragma unroll
            for (int j = 0; j < 4; j++)
                bv[j] = *(const int4*)&Bs[(buf * 64 + tx + 16 * j) * 32 + ((k4 ^ swz) * 4)];
            #pragma unroll
            for (int i = 0; i < 8; i++) {
                int4 av = *(const int4*)&As[(buf * 128 + ty * 8 + i) * 32 + k4 * 4];
                #pragma unroll
                for (int j = 0; j < 4; j++) {
                    iacc[i][j] = __dp4a(av.x, bv[j].x, iacc[i][j]);
                    iacc[i][j] = __dp4a(av.y, bv[j].y, iacc[i][j]);
                    iacc[i][j] = __dp4a(av.z, bv[j].z, iacc[i][j]);
                    iacc[i][j] = __dp4a(av.w, bv[j].w, iacc[i][j]);
                }
            }
        }
        #pragma unroll
        for (int j = 0; j < 4; j++) {
            float wsc = ws_s[(tx + 16 * j) * NGRP + g];
            #pragma unroll
            for (int i = 0; i < 8; i++) facc[i][j] += (float)iacc[i][j] * wsc;
        }
        __syncthreads();
    }

    #pragma unroll
    for (int i = 0; i < 8; i++) {
        int row = ty * 8 + i;
        float sval = sv_s[row];
        float* crow = C + (size_t)(rowBase + row) * N + colBase;
        #pragma unroll
        for (int j = 0; j < 4; j++) crow[tx + 16 * j] = facc[i][j] / sval;
    }
}

// ---------------- RMSNorm + RoPE (+ V copy), table-based ----------------
__global__ void post_kernel(const float* __restrict__ qnw, const float* __restrict__ knw) {
    int t = blockIdx.x, u = blockIdx.y, d = threadIdx.x;   // 128 threads
    const float* src;
    float* dst;
    const float* nw;
    if (u < NH) {
        src = &g_qkv[t * QKV_OUT + u * HD];
        dst = &g_qf[(t * NH + u) * HD];
        nw = qnw;
    } else if (u < NH + NKV) {
        int kv = u - NH;
        src = &g_qkv[t * QKV_OUT + NH * HD + kv * HD];
        dst = &g_kf[(t * NKV + kv) * HD];
        nw = knw;
    } else {
        int kv = u - NH - NKV;
        g_vf[(t * NKV + kv) * HD + d] = g_qkv[t * QKV_OUT + (NH + NKV) * HD + kv * HD + d];
        return;
    }
    __shared__ float buf[HD];
    __shared__ float red[4];
    float v = src[d];
    float sq = v * v;
    #pragma unroll
    for (int o = 16; o; o >>= 1) sq += __shfl_xor_sync(0xffffffffu, sq, o);
    if ((d & 31) == 0) red[d >> 5] = sq;
    __syncthreads();
    float mean = (red[0] + red[1] + red[2] + red[3]) * (1.f / 128.f);
    float r = rsqrtf(mean + 1e-5f);
    buf[d] = v * r * nw[d];
    __syncthreads();
    int p = d >> 1;
    float2 cs = g_rope[t * 64 + p];
    float x0 = buf[p * 2], x1 = buf[p * 2 + 1];
    dst[d] = (d & 1) ? (x0 * cs.y + x1 * cs.x) : (x0 * cs.x - x1 * cs.y);
}

// ---------------- causal GQA flash attention (fp32, f32x2 FMA) ----------------
#define SWZ(r, ch) ((r) * 32 + ((ch) ^ ((r) & 31)))
#define SMEM_ATTN (3 * 2048 * 16 + 64 * 68 * 4)

__global__ __launch_bounds__(256, 1) void attn_kernel() {
    extern __shared__ float4 smv[];
    float4* Qc = smv;            // 64 rows x 32 chunks (swizzled)
    float4* Kc = Qc + 2048;
    float4* Vc = Kc + 2048;
    float* Ps = (float*)(Vc + 2048);   // 64 x 68

    const int qt = blockIdx.x, hh = blockIdx.y;
    const int g = hh >> 2;
    const int tid = threadIdx.x;
    const int tx = tid & 15, ty = tid >> 4;
    const float scale = 0.08838834764831845f;   // 128^-0.5

    // load Q tile prescaled (swizzled float4)
    for (int i = tid; i < 2048; i += 256) {
        int r = i >> 5, ch = i & 31;
        float4 q = *(const float4*)&g_qf[((size_t)(qt * 64 + r) * NH + hh) * HD + ch * 4];
        q.x *= scale; q.y *= scale; q.z *= scale; q.w *= scale;
        Qc[SWZ(r, ch)] = q;
    }

    float m_i[4], l_i[4];
    unsigned long long o2[4][4];
    #pragma unroll
    for (int i = 0; i < 4; i++) {
        m_i[i] = -1e30f; l_i[i] = 0.f;
        #pragma unroll
        for (int k = 0; k < 4; k++) o2[i][k] = 0ull;
    }
    __syncthreads();

    for (int kt = 0; kt <= qt; kt++) {
        for (int i = tid; i < 2048; i += 256) {
            int r = i >> 5, ch = i & 31;
            Kc[SWZ(r, ch)] = *(const float4*)&g_kf[((size_t)(kt * 64 + r) * NKV + g) * HD + ch * 4];
            Vc[SWZ(r, ch)] = *(const float4*)&g_vf[((size_t)(kt * 64 + r) * NKV + g) * HD + ch * 4];
        }
        __syncthreads();

        // scores via packed f32x2: rows ty*4+i, cols tx*4+j
        unsigned long long s2[4][4];
        #pragma unroll
        for (int i = 0; i < 4; i++)
            #pragma unroll
            for (int j = 0; j < 4; j++) s2[i][j] = 0ull;
        #pragma unroll 4
        for (int ch = 0; ch < 32; ch++) {
            ulonglong2 q4[4], k4[4];
            #pragma unroll
            for (int i = 0; i < 4; i++) q4[i] = *(const ulonglong2*)&Qc[SWZ(ty * 4 + i, ch)];
            #pragma unroll
            for (int j = 0; j < 4; j++) k4[j] = *(const ulonglong2*)&Kc[SWZ(tx * 4 + j, ch)];
            #pragma unroll
            for (int i = 0; i < 4; i++)
                #pragma unroll
                for (int j = 0; j < 4; j++) {
                    fma2(s2[i][j], q4[i].x, k4[j].x);
                    fma2(s2[i][j], q4[i].y, k4[j].y);
                }
        }

        // fused online softmax: half-warp (width 16) owns each row
        float corr[4];
        #pragma unroll
        for (int i = 0; i < 4; i++) {
            int rg = qt * 64 + ty * 4 + i;
            float s[4];
            #pragma unroll
            for (int j = 0; j < 4; j++) {
                float2 t2 = upk2(s2[i][j]);
                float v = t2.x + t2.y;
                s[j] = (kt * 64 + tx * 4 + j <= rg) ? v : -1e30f;
            }
            float mt = fmaxf(fmaxf(s[0], s[1]), fmaxf(s[2], s[3]));
            #pragma unroll
            for (int o = 1; o < 16; o <<= 1) mt = fmaxf(mt, __shfl_xor_sync(0xffffffffu, mt, o, 16));
            float mn = fmaxf(m_i[i], mt);
            float p0 = expf(s[0] - mn), p1 = expf(s[1] - mn);
            float p2v = expf(s[2] - mn), p3 = expf(s[3] - mn);
            *(float4*)&Ps[(ty * 4 + i) * 68 + tx * 4] = make_float4(p0, p1, p2v, p3);
            float lt = (p0 + p1) + (p2v + p3);
            #pragma unroll
            for (int o = 1; o < 16; o <<= 1) lt += __shfl_xor_sync(0xffffffffu, lt, o, 16);
            corr[i] = expf(m_i[i] - mn);
            l_i[i] = l_i[i] * corr[i] + lt;
            m_i[i] = mn;
        }
        __syncthreads();

        // rescale + P @ V : rows ty*4+i, dims tx*8..tx*8+7 (packed pairs)
        #pragma unroll
        for (int i = 0; i < 4; i++) {
            unsigned long long c2 = pk2(corr[i], corr[i]);
            #pragma unroll
            for (int k = 0; k < 4; k++) o2[i][k] = mul2(o2[i][k], c2);
        }
        #pragma unroll 4
        for (int j = 0; j < 64; j++) {
            ulonglong2 va = *(const ulonglong2*)&Vc[j * 32 + ((2 * tx) ^ (j & 31))];
            ulonglong2 vb = *(const ulonglong2*)&Vc[j * 32 + ((2 * tx + 1) ^ (j & 31))];
            #pragma unroll
            for (int i = 0; i < 4; i++) {
                float p = Ps[(ty * 4 + i) * 68 + j];
                unsigned long long pp = pk2(p, p);
                fma2(o2[i][0], pp, va.x);
                fma2(o2[i][1], pp, va.y);
                fma2(o2[i][2], pp, vb.x);
                fma2(o2[i][3], pp, vb.y);
            }
        }
        __syncthreads();
    }

    #pragma unroll
    for (int i = 0; i < 4; i++) {
        float inv = 1.f / l_i[i];
        float2 a0 = upk2(o2[i][0]), a1 = upk2(o2[i][1]);
        float2 b0 = upk2(o2[i][2]), b1 = upk2(o2[i][3]);
        float* dst = &g_attn[(size_t)(qt * 64 + ty * 4 + i) * DIM + hh * HD + tx * 8];
        *(float4*)dst = make_float4(a0.x * inv, a0.y * inv, a1.x * inv, a1.y * inv);
        *(float4*)(dst + 4) = make_float4(b0.x * inv, b0.y * inv, b1.x * inv, b1.y * inv);
    }
}

// ---------------- launch ----------------
extern "C" void kernel_launch(void* const* d_in, const int* in_sizes, int n_in,
                              void* d_out, int out_size) {
    const float* x      = (const float*)d_in[0];
    const float* w_qkv  = (const float*)d_in[1];
    const float* ws_qkv = (const float*)d_in[2];
    const float* w_o    = (const float*)d_in[3];
    const float* ws_o   = (const float*)d_in[4];
    const float* qnw    = (const float*)d_in[5];
    const float* knw    = (const float*)d_in[6];
    float* out = (float*)d_out;

    cudaFuncSetAttribute(attn_kernel, cudaFuncAttributeMaxDynamicSharedMemorySize, SMEM_ATTN);
    cudaFuncSetAttribute(gemm_i8_kernel, cudaFuncAttributeMaxDynamicSharedMemorySize, GEMM_SMEM);

    conv_w_kernel<<<2048, 256>>>(w_qkv, QKV_OUT, 0);
    conv_w_kernel<<<2048, 256>>>(w_o, DIM, 1);
    rope_kernel<<<256, 256>>>();
    quant_kernel<<<S_TOK, 256>>>(x, 0);
    gemm_i8_kernel<<<dim3(QKV_OUT / 64, S_TOK / 128), 256, GEMM_SMEM>>>(0, ws_qkv, nullptr, QKV_OUT);
    post_kernel<<<dim3(S_TOK, NH + 2 * NKV), 128>>>(qnw, knw);
    attn_kernel<<<dim3(S_TOK / 64, NH), 256, SMEM_ATTN>>>();
    quant_kernel<<<S_TOK, 256>>>(nullptr, 1);
    gemm_i8_kernel<<<dim3(DIM / 64, S_TOK / 128), 256, GEMM_SMEM>>>(1, ws_o, out, DIM);
}

// round 6
// speedup vs baseline: 1.6273x; 1.0091x over previous
#include <cuda_runtime.h>
#include <cuda_bf16.h>
#include <math.h>
#include <stdint.h>

#define S_TOK   1024
#define DIM     2560
#define HD      128
#define NH      20
#define NKV     5
#define QKV_OUT 3840
#define KW      640      // K in int32 words (2560/4)
#define NGRP    20       // scale groups (2560/128)

// ---------------- device scratch (static, no allocation) ----------------
__device__ int    g_wq[QKV_OUT * KW];
__device__ int    g_wo[DIM * KW];
__device__ int    g_qx[S_TOK * KW];
__device__ float  g_sx[S_TOK];
__device__ float  g_qkv[S_TOK * QKV_OUT];
__device__ float  g_qf[S_TOK * NH * HD];
__device__ float  g_kf[S_TOK * NKV * HD];
__device__ float  g_vf[S_TOK * NKV * HD];
__device__ float  g_attn[S_TOK * NH * HD];
__device__ int    g_qa[S_TOK * KW];
__device__ float  g_sa[S_TOK];
__device__ float2 g_rope[S_TOK * 64];

// ---------------- f32x2 helpers ----------------
__device__ __forceinline__ void fma2(unsigned long long& d, unsigned long long a,
                                     unsigned long long b) {
    asm("fma.rn.f32x2 %0, %1, %2, %3;" : "=l"(d) : "l"(a), "l"(b), "l"(d));
}
__device__ __forceinline__ unsigned long long mul2(unsigned long long a,
                                                   unsigned long long b) {
    unsigned long long d;
    asm("mul.rn.f32x2 %0, %1, %2;" : "=l"(d) : "l"(a), "l"(b));
    return d;
}
__device__ __forceinline__ unsigned long long pk2(float lo, float hi) {
    unsigned long long r;
    asm("mov.b64 %0, {%1, %2};" : "=l"(r) : "r"(__float_as_uint(lo)), "r"(__float_as_uint(hi)));
    return r;
}
__device__ __forceinline__ float2 upk2(unsigned long long v) {
    unsigned lo, hi;
    asm("mov.b64 {%0, %1}, %2;" : "=r"(lo), "=r"(hi) : "l"(v));
    return make_float2(__uint_as_float(lo), __uint_as_float(hi));
}

// ---------------- cp.async helpers ----------------
#define CP16(dst, src)                                                          \
    do {                                                                        \
        unsigned _sa = (unsigned)__cvta_generic_to_shared(dst);                 \
        asm volatile("cp.async.cg.shared.global [%0], [%1], 16;" ::"r"(_sa),    \
                     "l"(src));                                                 \
    } while (0)
#define CPCOMMIT() asm volatile("cp.async.commit_group;")
#define CPWAIT1()  asm volatile("cp.async.wait_group 1;")
#define CPWAIT0()  asm volatile("cp.async.wait_group 0;")

// ---------------- int8 mma.sync (baseline PTX, tensor pipe) ----------------
__device__ __forceinline__ void mma_s8(int& c0, int& c1, int& c2, int& c3,
                                       int a0, int a1, int a2, int a3,
                                       int b0, int b1) {
    asm volatile(
        "mma.sync.aligned.m16n8k32.row.col.s32.s8.s8.s32 "
        "{%0,%1,%2,%3}, {%4,%5,%6,%7}, {%8,%9}, {%0,%1,%2,%3};"
        : "+r"(c0), "+r"(c1), "+r"(c2), "+r"(c3)
        : "r"(a0), "r"(a1), "r"(a2), "r"(a3), "r"(b0), "r"(b1));
}

// ---------------- ternary weight f32 -> packed int8 (vectorized) ----------------
__global__ void conv_w_kernel(const float* __restrict__ w, int rows, int which) {
    int* dst = which ? g_wo : g_wq;
    int total = rows * KW;
    for (int i = blockIdx.x * blockDim.x + threadIdx.x; i < total;
         i += gridDim.x * blockDim.x) {
        float4 v = *(const float4*)&w[(size_t)i * 4];
        int b0 = (int)v.x, b1 = (int)v.y, b2 = (int)v.z, b3 = (int)v.w;
        dst[i] = (b0 & 0xFF) | ((b1 & 0xFF) << 8) | ((b2 & 0xFF) << 16) | ((b3 & 0xFF) << 24);
    }
}

// ---------------- RoPE table (double precision, tiny) ----------------
__global__ void rope_kernel() {
    int idx = blockIdx.x * 256 + threadIdx.x;   // 65536 total
    int t = idx >> 6, p = idx & 63;
    double inv = exp(-(double)p / 64.0 * log(500000.0));
    double ang = (double)t * inv;
    g_rope[idx] = make_float2((float)cos(ang), (float)sin(ang));
}

// ---------------- per-token activation quant (vectorized) ----------------
__global__ void quant_kernel(const float* __restrict__ xsrc, int which) {
    int t = blockIdx.x;
    const float4* row = which ? (const float4*)&g_attn[t * DIM]
                              : (const float4*)(xsrc + (size_t)t * DIM);
    __shared__ float red[8];
    float m = 0.f;
    for (int i = threadIdx.x; i < KW; i += 256) {
        float4 v = row[i];
        m = fmaxf(m, fmaxf(fmaxf(fabsf(v.x), fabsf(v.y)), fmaxf(fabsf(v.z), fabsf(v.w))));
    }
    #pragma unroll
    for (int o = 16; o; o >>= 1) m = fmaxf(m, __shfl_xor_sync(0xffffffffu, m, o));
    if ((threadIdx.x & 31) == 0) red[threadIdx.x >> 5] = m;
    __syncthreads();
    if (threadIdx.x < 8) {
        m = red[threadIdx.x];
        #pragma unroll
        for (int o = 4; o; o >>= 1) m = fmaxf(m, __shfl_xor_sync(0xffu, m, o));
        if (threadIdx.x == 0) red[0] = m;
    }
    __syncthreads();
    m = fmaxf(red[0], 1e-5f);
    float s = 127.f / m;
    if (threadIdx.x == 0) { if (which) g_sa[t] = s; else g_sx[t] = s; }
    int* q = (which ? g_qa : g_qx) + t * KW;
    for (int w = threadIdx.x; w < KW; w += 256) {
        float4 v = row[w];
        int q0 = min(127, max(-128, (int)rintf(v.x * s)));
        int q1 = min(127, max(-128, (int)rintf(v.y * s)));
        int q2 = min(127, max(-128, (int)rintf(v.z * s)));
        int q3 = min(127, max(-128, (int)rintf(v.w * s)));
        q[w] = (q0 & 0xFF) | ((q1 & 0xFF) << 8) | ((q2 & 0xFF) << 16) | ((q3 & 0xFF) << 24);
    }
}

// ---------------- mma.sync int8 group-scaled GEMM ----------------
// CTA tile 128x64, 8 warps each 32x32 (2x4 m16n8k32 tiles).
// Smem rows padded to 144B -> conflict-free per-lane fragment LDS.
#define ASTRIDE 144
#define A_BUF   (128 * ASTRIDE)
#define B_BUF   (64 * ASTRIDE)
#define WS_OFF  0
#define SV_OFF  (64 * NGRP * 4)
#define A_OFF   (SV_OFF + 512)
#define B_OFF   (A_OFF + 2 * A_BUF)
#define GEMM_SMEM (B_OFF + 2 * B_BUF)

__global__ __launch_bounds__(256, 1) void gemm_mma_kernel(int which,
                                                          const float* __restrict__ ws,
                                                          float* __restrict__ dOut, int N) {
    const int* __restrict__ Aq = which ? g_qa : g_qx;
    const int* __restrict__ Bw = which ? g_wo : g_wq;
    const float* __restrict__ sv = which ? g_sa : g_sx;
    float* __restrict__ C = which ? dOut : g_qkv;

    extern __shared__ char sm[];
    float* ws_s = (float*)(sm + WS_OFF);   // [g][col] 20x64
    float* sv_s = (float*)(sm + SV_OFF);   // 128

    const int tid = threadIdx.x, wid = tid >> 5, lane = tid & 31;
    const int g4 = lane >> 2, tig = lane & 3;
    const int warpM = (wid & 3) * 32, warpN = (wid >> 2) * 32;
    const int rowBase = blockIdx.y * 128, colBase = blockIdx.x * 64;

    for (int i = tid; i < 64 * NGRP; i += 256) {
        int c = i / NGRP, g = i - c * NGRP;
        ws_s[g * 64 + c] = ws[(size_t)(colBase + c) * NGRP + g];
    }
    if (tid < 128) sv_s[tid] = sv[rowBase + tid];

    const int* Abase = Aq + (size_t)rowBase * KW;
    const int* Bbase = Bw + (size_t)colBase * KW;

    auto issue = [&](int g, int b) {
        #pragma unroll
        for (int u = 0; u < 4; u++) {
            int c = tid + 256 * u;
            int r = c >> 3, c16 = c & 7;
            CP16(sm + A_OFF + b * A_BUF + r * ASTRIDE + c16 * 16,
                 Abase + r * KW + g * 32 + c16 * 4);
        }
        #pragma unroll
        for (int u = 0; u < 2; u++) {
            int c = tid + 256 * u;
            int r = c >> 3, c16 = c & 7;
            CP16(sm + B_OFF + b * B_BUF + r * ASTRIDE + c16 * 16,
                 Bbase + r * KW + g * 32 + c16 * 4);
        }
        CPCOMMIT();
    };

    float facc[2][4][4];
    #pragma unroll
    for (int mt = 0; mt < 2; mt++)
        #pragma unroll
        for (int nt = 0; nt < 4; nt++)
            #pragma unroll
            for (int k = 0; k < 4; k++) facc[mt][nt][k] = 0.f;

    issue(0, 0);

    for (int g = 0; g < NGRP; g++) {
        int b = g & 1;
        if (g + 1 < NGRP) { issue(g + 1, b ^ 1); CPWAIT1(); } else { CPWAIT0(); }
        __syncthreads();

        const char* smA = sm + A_OFF + b * A_BUF;
        const char* smB = sm + B_OFF + b * B_BUF;
        int acc[2][4][4] = {};
        #pragma unroll
        for (int ks = 0; ks < 4; ks++) {
            int kb = ks * 32 + tig * 4;
            int a[2][4], bb[4][2];
            #pragma unroll
            for (int mt = 0; mt < 2; mt++) {
                int ra = warpM + mt * 16 + g4;
                a[mt][0] = *(const int*)(smA + ra * ASTRIDE + kb);
                a[mt][1] = *(const int*)(smA + (ra + 8) * ASTRIDE + kb);
                a[mt][2] = *(const int*)(smA + ra * ASTRIDE + kb + 16);
                a[mt][3] = *(const int*)(smA + (ra + 8) * ASTRIDE + kb + 16);
            }
            #pragma unroll
            for (int nt = 0; nt < 4; nt++) {
                int cn = warpN + nt * 8 + g4;
                bb[nt][0] = *(const int*)(smB + cn * ASTRIDE + kb);
                bb[nt][1] = *(const int*)(smB + cn * ASTRIDE + kb + 16);
            }
            #pragma unroll
            for (int mt = 0; mt < 2; mt++)
                #pragma unroll
                for (int nt = 0; nt < 4; nt++)
                    mma_s8(acc[mt][nt][0], acc[mt][nt][1], acc[mt][nt][2], acc[mt][nt][3],
                           a[mt][0], a[mt][1], a[mt][2], a[mt][3], bb[nt][0], bb[nt][1]);
        }
        #pragma unroll
        for (int nt = 0; nt < 4; nt++) {
            float2 w2 = *(const float2*)&ws_s[g * 64 + warpN + nt * 8 + tig * 2];
            #pragma unroll
            for (int mt = 0; mt < 2; mt++) {
                facc[mt][nt][0] += (float)acc[mt][nt][0] * w2.x;
                facc[mt][nt][1] += (float)acc[mt][nt][1] * w2.y;
                facc[mt][nt][2] += (float)acc[mt][nt][2] * w2.x;
                facc[mt][nt][3] += (float)acc[mt][nt][3] * w2.y;
            }
        }
        __syncthreads();
    }

    #pragma unroll
    for (int mt = 0; mt < 2; mt++) {
        int r0 = warpM + mt * 16 + g4, r1 = r0 + 8;
        float inv0 = 1.f / sv_s[r0], inv1 = 1.f / sv_s[r1];
        #pragma unroll
        for (int nt = 0; nt < 4; nt++) {
            int col = colBase + warpN + nt * 8 + tig * 2;
            *(float2*)&C[(size_t)(rowBase + r0) * N + col] =
                make_float2(facc[mt][nt][0] * inv0, facc[mt][nt][1] * inv0);
            *(float2*)&C[(size_t)(rowBase + r1) * N + col] =
                make_float2(facc[mt][nt][2] * inv1, facc[mt][nt][3] * inv1);
        }
    }
}

// ---------------- RMSNorm + RoPE (+ V copy), table-based ----------------
__global__ void post_kernel(const float* __restrict__ qnw, const float* __restrict__ knw) {
    int t = blockIdx.x, u = blockIdx.y, d = threadIdx.x;   // 128 threads
    const float* src;
    float* dst;
    const float* nw;
    if (u < NH) {
        src = &g_qkv[t * QKV_OUT + u * HD];
        dst = &g_qf[(t * NH + u) * HD];
        nw = qnw;
    } else if (u < NH + NKV) {
        int kv = u - NH;
        src = &g_qkv[t * QKV_OUT + NH * HD + kv * HD];
        dst = &g_kf[(t * NKV + kv) * HD];
        nw = knw;
    } else {
        int kv = u - NH - NKV;
        g_vf[(t * NKV + kv) * HD + d] = g_qkv[t * QKV_OUT + (NH + NKV) * HD + kv * HD + d];
        return;
    }
    __shared__ float buf[HD];
    __shared__ float red[4];
    float v = src[d];
    float sq = v * v;
    #pragma unroll
    for (int o = 16; o; o >>= 1) sq += __shfl_xor_sync(0xffffffffu, sq, o);
    if ((d & 31) == 0) red[d >> 5] = sq;
    __syncthreads();
    float mean = (red[0] + red[1] + red[2] + red[3]) * (1.f / 128.f);
    float r = rsqrtf(mean + 1e-5f);
    buf[d] = v * r * nw[d];
    __syncthreads();
    int p = d >> 1;
    float2 cs = g_rope[t * 64 + p];
    float x0 = buf[p * 2], x1 = buf[p * 2 + 1];
    dst[d] = (d & 1) ? (x0 * cs.y + x1 * cs.x) : (x0 * cs.x - x1 * cs.y);
}

// ---------------- causal GQA flash attention (fp32, f32x2 FMA) ----------------
#define SWZ(r, ch) ((r) * 32 + ((ch) ^ ((r) & 31)))
#define SMEM_ATTN (3 * 2048 * 16 + 64 * 68 * 4)

__global__ __launch_bounds__(256, 1) void attn_kernel() {
    extern __shared__ float4 smv[];
    float4* Qc = smv;            // 64 rows x 32 chunks (swizzled)
    float4* Kc = Qc + 2048;
    float4* Vc = Kc + 2048;
    float* Ps = (float*)(Vc + 2048);   // 64 x 68

    const int qt = blockIdx.x, hh = blockIdx.y;
    const int g = hh >> 2;
    const int tid = threadIdx.x;
    const int tx = tid & 15, ty = tid >> 4;
    const float scale = 0.08838834764831845f;   // 128^-0.5

    for (int i = tid; i < 2048; i += 256) {
        int r = i >> 5, ch = i & 31;
        float4 q = *(const float4*)&g_qf[((size_t)(qt * 64 + r) * NH + hh) * HD + ch * 4];
        q.x *= scale; q.y *= scale; q.z *= scale; q.w *= scale;
        Qc[SWZ(r, ch)] = q;
    }

    float m_i[4], l_i[4];
    unsigned long long o2[4][4];
    #pragma unroll
    for (int i = 0; i < 4; i++) {
        m_i[i] = -1e30f; l_i[i] = 0.f;
        #pragma unroll
        for (int k = 0; k < 4; k++) o2[i][k] = 0ull;
    }
    __syncthreads();

    for (int kt = 0; kt <= qt; kt++) {
        for (int i = tid; i < 2048; i += 256) {
            int r = i >> 5, ch = i & 31;
            Kc[SWZ(r, ch)] = *(const float4*)&g_kf[((size_t)(kt * 64 + r) * NKV + g) * HD + ch * 4];
            Vc[SWZ(r, ch)] = *(const float4*)&g_vf[((size_t)(kt * 64 + r) * NKV + g) * HD + ch * 4];
        }
        __syncthreads();

        unsigned long long s2[4][4];
        #pragma unroll
        for (int i = 0; i < 4; i++)
            #pragma unroll
            for (int j = 0; j < 4; j++) s2[i][j] = 0ull;
        #pragma unroll 4
        for (int ch = 0; ch < 32; ch++) {
            ulonglong2 q4[4], k4[4];
            #pragma unroll
            for (int i = 0; i < 4; i++) q4[i] = *(const ulonglong2*)&Qc[SWZ(ty * 4 + i, ch)];
            #pragma unroll
            for (int j = 0; j < 4; j++) k4[j] = *(const ulonglong2*)&Kc[SWZ(tx * 4 + j, ch)];
            #pragma unroll
            for (int i = 0; i < 4; i++)
                #pragma unroll
                for (int j = 0; j < 4; j++) {
                    fma2(s2[i][j], q4[i].x, k4[j].x);
                    fma2(s2[i][j], q4[i].y, k4[j].y);
                }
        }

        float corr[4];
        #pragma unroll
        for (int i = 0; i < 4; i++) {
            int rg = qt * 64 + ty * 4 + i;
            float s[4];
            #pragma unroll
            for (int j = 0; j < 4; j++) {
                float2 t2 = upk2(s2[i][j]);
                float v = t2.x + t2.y;
                s[j] = (kt * 64 + tx * 4 + j <= rg) ? v : -1e30f;
            }
            float mt = fmaxf(fmaxf(s[0], s[1]), fmaxf(s[2], s[3]));
            #pragma unroll
            for (int o = 1; o < 16; o <<= 1) mt = fmaxf(mt, __shfl_xor_sync(0xffffffffu, mt, o, 16));
            float mn = fmaxf(m_i[i], mt);
            float p0 = expf(s[0] - mn), p1 = expf(s[1] - mn);
            float p2v = expf(s[2] - mn), p3 = expf(s[3] - mn);
            *(float4*)&Ps[(ty * 4 + i) * 68 + tx * 4] = make_float4(p0, p1, p2v, p3);
            float lt = (p0 + p1) + (p2v + p3);
            #pragma unroll
            for (int o = 1; o < 16; o <<= 1) lt += __shfl_xor_sync(0xffffffffu, lt, o, 16);
            corr[i] = expf(m_i[i] - mn);
            l_i[i] = l_i[i] * corr[i] + lt;
            m_i[i] = mn;
        }
        __syncthreads();

        #pragma unroll
        for (int i = 0; i < 4; i++) {
            unsigned long long c2 = pk2(corr[i], corr[i]);
            #pragma unroll
            for (int k = 0; k < 4; k++) o2[i][k] = mul2(o2[i][k], c2);
        }
        #pragma unroll 4
        for (int j = 0; j < 64; j++) {
            ulonglong2 va = *(const ulonglong2*)&Vc[j * 32 + ((2 * tx) ^ (j & 31))];
            ulonglong2 vb = *(const ulonglong2*)&Vc[j * 32 + ((2 * tx + 1) ^ (j & 31))];
            #pragma unroll
            for (int i = 0; i < 4; i++) {
                float p = Ps[(ty * 4 + i) * 68 + j];
                unsigned long long pp = pk2(p, p);
                fma2(o2[i][0], pp, va.x);
                fma2(o2[i][1], pp, va.y);
                fma2(o2[i][2], pp, vb.x);
                fma2(o2[i][3], pp, vb.y);
            }
        }
        __syncthreads();
    }

    #pragma unroll
    for (int i = 0; i < 4; i++) {
        float inv = 1.f / l_i[i];
        float2 a0 = upk2(o2[i][0]), a1 = upk2(o2[i][1]);
        float2 b0 = upk2(o2[i][2]), b1 = upk2(o2[i][3]);
        float* dst = &g_attn[(size_t)(qt * 64 + ty * 4 + i) * DIM + hh * HD + tx * 8];
        *(float4*)dst = make_float4(a0.x * inv, a0.y * inv, a1.x * inv, a1.y * inv);
        *(float4*)(dst + 4) = make_float4(b0.x * inv, b0.y * inv, b1.x * inv, b1.y * inv);
    }
}

// ---------------- launch ----------------
extern "C" void kernel_launch(void* const* d_in, const int* in_sizes, int n_in,
                              void* d_out, int out_size) {
    const float* x      = (const float*)d_in[0];
    const float* w_qkv  = (const float*)d_in[1];
    const float* ws_qkv = (const float*)d_in[2];
    const float* w_o    = (const float*)d_in[3];
    const float* ws_o   = (const float*)d_in[4];
    const float* qnw    = (const float*)d_in[5];
    const float* knw    = (const float*)d_in[6];
    float* out = (float*)d_out;

    cudaFuncSetAttribute(attn_kernel, cudaFuncAttributeMaxDynamicSharedMemorySize, SMEM_ATTN);
    cudaFuncSetAttribute(gemm_mma_kernel, cudaFuncAttributeMaxDynamicSharedMemorySize, GEMM_SMEM);

    conv_w_kernel<<<2048, 256>>>(w_qkv, QKV_OUT, 0);
    conv_w_kernel<<<2048, 256>>>(w_o, DIM, 1);
    rope_kernel<<<256, 256>>>();
    quant_kernel<<<S_TOK, 256>>>(x, 0);
    gemm_mma_kernel<<<dim3(QKV_OUT / 64, S_TOK / 128), 256, GEMM_SMEM>>>(0, ws_qkv, nullptr, QKV_OUT);
    post_kernel<<<dim3(S_TOK, NH + 2 * NKV), 128>>>(qnw, knw);
    attn_kernel<<<dim3(S_TOK / 64, NH), 256, SMEM_ATTN>>>();
    quant_kernel<<<S_TOK, 256>>>(nullptr, 1);
    gemm_mma_kernel<<<dim3(DIM / 64, S_TOK / 128), 256, GEMM_SMEM>>>(1, ws_o, out, DIM);
}